// round 12
// baseline (speedup 1.0000x reference)
#include <cuda_runtime.h>

#define U_N    100000
#define I_N    30000
#define NB     3
#define D_N    64
#define D2     128
#define NE_UI  500000
#define NE_IG  400000
#define NE_TR  1000000
#define NE_ALL (NB * NE_IG + NE_TR)
#define NBATCH 2048
#define NK     20
#define BK     128
#define CNT_N  ((NB + 1) * I_N)
#define EPSF   1e-8f
#define REGF   1e-4f

// ---------------- scratch (device globals; no allocation) ------------------
__device__ __align__(16) float g_ii   [NB * I_N * D_N];   // (A_ii@item_emb)/deg
__device__ __align__(16) float g_if   [I_N * D_N];        // train^T @ user_emb
__device__ __align__(16) float g_itf  [I_N * D2];
__device__               float g_itfn [I_N];
__device__               int   g_u2slot[U_N];
__device__ __align__(16) float g_n2u  [NB * NBATCH * D2]; // RAW [A|B] accumulation
__device__ __align__(16) float g_i2u  [NB * NBATCH * D2]; // (n2u@W2)*inv_denom
__device__ __align__(16) float g_uf   [NBATCH * D2];
__device__               float g_sw   [NBATCH];
__device__               float g_ufn  [NBATCH];
__device__ __align__(16) float g_W1   [NB * D2 * D2];     // [ibW_top ; Wp@ibW_bot]
__device__ __align__(16) float g_W2   [NB * D2 * D2];     // + output-side Wp fold
// bucketed adjacency: rows 0..3*I_N-1 = ig behaviors, rows 3*I_N.. = train
__device__               int   g_cnt  [CNT_N + 1];        // +1: nhit counter
__device__               int   g_bkt  [(size_t)CNT_N * BK];
__device__               int   g_hit  [NB * NE_UI];

__device__ __forceinline__ void red_add4(float* p, float4 v) {
#if defined(__CUDA_ARCH__) && (__CUDA_ARCH__ >= 900)
    asm volatile("red.global.add.v4.f32 [%0], {%1,%2,%3,%4};"
                 :: "l"(p), "f"(v.x), "f"(v.y), "f"(v.z), "f"(v.w) : "memory");
#else
    atomicAdd(p + 0, v.x); atomicAdd(p + 1, v.y);
    atomicAdd(p + 2, v.z); atomicAdd(p + 3, v.w);
#endif
}

// ---------------- kernels --------------------------------------------------

// W1[:, c0..c0+32): top rows = ibW copy, bottom rows = Wp @ ibW_bot (smem GEMM)
__global__ void k_w1a(const float* __restrict__ ibW, const float* __restrict__ ipW) {
    int bi = blockIdx.y;
    int c0 = blockIdx.x * 32;
    const float* ibWb = ibW + (size_t)bi * D2 * D2;
    const float* wp   = ipW + (size_t)bi * D_N * D_N;
    __shared__ float shWpT[64 * 64];   // WpT[k][r] = Wp[r][k]
    __shared__ float shB[64 * 32];     // ibW_bot[k][c0+c]
    int t = threadIdx.x;               // 256
    for (int p = t; p < 64 * 64; p += 256) {
        int r = p >> 6, k = p & 63;
        shWpT[k * 64 + r] = wp[p];
    }
    for (int p = t; p < 64 * 32; p += 256) {
        int k = p >> 5, c = p & 31;
        shB[p] = ibWb[(size_t)(64 + k) * D2 + c0 + c];
    }
    __syncthreads();
    float* W1b = g_W1 + (size_t)bi * D2 * D2;
    // top copy (rows 0..63)
    for (int p = t; p < 64 * 32; p += 256) {
        int r = p >> 5, c = p & 31;
        W1b[r * D2 + c0 + c] = ibWb[r * D2 + c0 + c];
    }
    // bottom GEMM: 64 rows x 32 cols, 8 outputs/thread
    int r = t & 63, cq = (t >> 6) * 8;
    float acc[8];
    #pragma unroll
    for (int j = 0; j < 8; j++) acc[j] = 0.f;
    for (int k = 0; k < 64; k++) {
        float w = shWpT[k * 64 + r];
        #pragma unroll
        for (int j = 0; j < 8; j++) acc[j] += w * shB[k * 32 + cq + j];
    }
    #pragma unroll
    for (int j = 0; j < 8; j++)
        W1b[(64 + r) * D2 + c0 + cq + j] = acc[j];
}

// W2[:, c0..c0+32): cols<64 copy of W1; cols>=64: W1[:,64:] @ Wp^T (smem GEMM)
__global__ void k_w1b(const float* __restrict__ ipW) {
    int bi = blockIdx.y;
    int c0 = blockIdx.x * 32;
    const float* W1b = g_W1 + (size_t)bi * D2 * D2;
    float* W2b = g_W2 + (size_t)bi * D2 * D2;
    int t = threadIdx.x;               // 256
    if (c0 < 64) {                     // copy slice
        for (int p = t; p < D2 * 32; p += 256) {
            int k = p >> 5, c = p & 31;
            W2b[k * D2 + c0 + c] = W1b[k * D2 + c0 + c];
        }
        return;
    }
    int r0 = c0 - 64;                  // output r in [r0, r0+32)
    const float* wp = ipW + (size_t)bi * D_N * D_N;
    __shared__ float shW1rT[64 * D2];  // [j][k] = W1[k][64+j]   (32KB)
    __shared__ float shWpT [64 * 32];  // [j][r-r0] = Wp[r][j]   (8KB)
    for (int p = t; p < 64 * D2; p += 256) {
        int j = p >> 7, k = p & 127;
        shW1rT[j * D2 + k] = W1b[k * D2 + 64 + j];
    }
    for (int p = t; p < 64 * 32; p += 256) {
        int j = p >> 5, r = p & 31;
        shWpT[p] = wp[(r0 + r) * D_N + j];
    }
    __syncthreads();
    int k = t & 127, rq = (t >> 7) * 16;   // 16 outputs/thread
    float acc[16];
    #pragma unroll
    for (int q = 0; q < 16; q++) acc[q] = 0.f;
    for (int j = 0; j < 64; j++) {
        float w1v = shW1rT[j * D2 + k];
        #pragma unroll
        for (int q = 0; q < 16; q++) acc[q] += w1v * shWpT[j * 32 + rq + q];
    }
    #pragma unroll
    for (int q = 0; q < 16; q++)
        W2b[k * D2 + 64 + r0 + rq + q] = acc[q];
}

__global__ void k_scatter(const int* __restrict__ user, float* out, int out_size) {
    int b = blockIdx.x * blockDim.x + threadIdx.x;
    if (b < NBATCH) atomicMin(&g_u2slot[user[b]], b);
    if (b == 0 && out_size > NBATCH * NK) out[NBATCH * NK] = 0.f;
}

// fused bucket fill, 8 edges/thread (8 independent atomic chains for MLP)
__global__ void k_fillb(const int* __restrict__ ig_rows, const int* __restrict__ ig_cols,
                        const int* __restrict__ trows, const int* __restrict__ tcols) {
    int i = (blockIdx.x * blockDim.x + threadIdx.x) * 8;
    if (i >= NE_ALL) return;
    const int *rbase, *cbase;
    int base;
    if (i < NB * NE_IG) {              // NE_IG % 8 == 0: uniform behavior per group
        rbase = ig_rows + i; cbase = ig_cols + i;
        base = (i / NE_IG) * I_N;
    } else {
        int j = i - NB * NE_IG;
        rbase = tcols + j; cbase = trows + j;   // dest=item, src=user
        base = NB * I_N;
    }
    int4 ra = ((const int4*)rbase)[0], rb = ((const int4*)rbase)[1];
    int4 ca = ((const int4*)cbase)[0], cb = ((const int4*)cbase)[1];
    int rr[8] = {ra.x, ra.y, ra.z, ra.w, rb.x, rb.y, rb.z, rb.w};
    int cc[8] = {ca.x, ca.y, ca.z, ca.w, cb.x, cb.y, cb.z, cb.w};
    #pragma unroll
    for (int j = 0; j < 8; j++) {
        int row = base + rr[j];
        int slot = atomicAdd(&g_cnt[row], 1);
        if (slot < BK) g_bkt[(size_t)row * BK + slot] = cc[j];
    }
}

// fused warp-per-row gather (ig rows -> g_ii, train rows -> g_if)
__global__ void k_gather(const float* __restrict__ iemb, const float* __restrict__ uemb,
                         const float* __restrict__ deg) {
    int w = (blockIdx.x * blockDim.x + threadIdx.x) >> 5;
    int lane = threadIdx.x & 31;
    if (w >= CNT_N) return;
    int bi = w / I_N, r = w - bi * I_N;
    int cnt = g_cnt[w]; if (cnt > BK) cnt = BK;
    const int* src = g_bkt + (size_t)w * BK;
    const float* emb = (bi < NB) ? iemb : uemb;
    float2 a0 = {0.f, 0.f}, a1 = {0.f, 0.f}, a2 = {0.f, 0.f}, a3 = {0.f, 0.f};
    for (int j = 0; j < cnt; j += 32) {
        int m = cnt - j; if (m > 32) m = 32;
        int sidx = (lane < m) ? src[j + lane] : 0;
        int q = 0;
        for (; q + 4 <= m; q += 4) {
            int s0 = __shfl_sync(0xffffffffu, sidx, q);
            int s1 = __shfl_sync(0xffffffffu, sidx, q + 1);
            int s2 = __shfl_sync(0xffffffffu, sidx, q + 2);
            int s3 = __shfl_sync(0xffffffffu, sidx, q + 3);
            float2 v0 = ((const float2*)(emb + (size_t)s0 * D_N))[lane];
            float2 v1 = ((const float2*)(emb + (size_t)s1 * D_N))[lane];
            float2 v2 = ((const float2*)(emb + (size_t)s2 * D_N))[lane];
            float2 v3 = ((const float2*)(emb + (size_t)s3 * D_N))[lane];
            a0.x += v0.x; a0.y += v0.y;  a1.x += v1.x; a1.y += v1.y;
            a2.x += v2.x; a2.y += v2.y;  a3.x += v3.x; a3.y += v3.y;
        }
        for (; q < m; q++) {
            int s = __shfl_sync(0xffffffffu, sidx, q);
            float2 v = ((const float2*)(emb + (size_t)s * D_N))[lane];
            a0.x += v.x; a0.y += v.y;
        }
    }
    float2 acc = {a0.x + a1.x + a2.x + a3.x, a0.y + a1.y + a2.y + a3.y};
    if (bi < NB) {
        float inv = 1.f / (deg[w] + EPSF);   // deg laid out [NB][I_N] == w
        acc.x *= inv; acc.y *= inv;
        ((float2*)(g_ii + (size_t)w * D_N))[lane] = acc;
    } else {
        ((float2*)(g_if + (size_t)r * D_N))[lane] = acc;
    }
}

// scan ui edges, compact hits (slot,col) keys (warp-aggregated append)
__global__ void k_filter(const int* __restrict__ rows, const int* __restrict__ cols) {
    int i = (blockIdx.x * blockDim.x + threadIdx.x) * 4;
    int lane = threadIdx.x & 31;
    bool in = (i < NB * NE_UI);
    int4 r = in ? *(const int4*)(rows + i) : make_int4(0, 0, 0, 0);
    int bi = in ? (i / NE_UI) : 0;
    int rb = bi * NBATCH;
    int rr[4] = {r.x, r.y, r.z, r.w};
    #pragma unroll
    for (int j = 0; j < 4; j++) {
        int sl = in ? g_u2slot[rr[j]] : 0x7fffffff;
        bool hit = sl < NBATCH;
        unsigned m = __ballot_sync(0xffffffffu, hit);
        if (m) {
            int leader = __ffs(m) - 1;
            int base;
            if (lane == leader) base = atomicAdd(&g_cnt[CNT_N], __popc(m));
            base = __shfl_sync(0xffffffffu, base, leader);
            if (hit) {
                int col = cols[i + j];
                g_hit[base + __popc(m & ((1u << lane) - 1))] = ((rb + sl) << 15) | col;
            }
        }
    }
}

// accumulate hit edges: n2u[rs] += [item_emb[col] | g_ii[bi][col]]  (RAW)
__global__ void k_ui_accum(const float* __restrict__ iemb) {
    int nw = (gridDim.x * blockDim.x) >> 5;
    int w = (blockIdx.x * blockDim.x + threadIdx.x) >> 5;
    int lane = threadIdx.x & 31;
    int n = g_cnt[CNT_N];
    for (int h = w; h < n; h += nw) {
        int key = g_hit[h];
        int col = key & 0x7fff;
        int rs = key >> 15;
        int bi = rs >> 11;
        float* base = g_n2u + (size_t)rs * D2;
        float4 v;
        float* dst;
        if (lane < 16) {
            v = ((const float4*)(iemb + (size_t)col * D_N))[lane];
            dst = base + lane * 4;
        } else {
            v = ((const float4*)(g_ii + (size_t)(bi * I_N + col) * D_N))[lane - 16];
            dst = base + 64 + (lane - 16) * 4;
        }
        red_add4(dst, v);
    }
}

// i2u[bi][s] = (raw_n2u[bi][s] @ W2[bi]) * inv_denom[bi][s]   (norm fused)
__global__ void k_i2u(const float* __restrict__ ubd, const int* __restrict__ user) {
    int bi = blockIdx.y;
    int s0 = blockIdx.x * 32;
    const float* Wb = g_W2 + (size_t)bi * D2 * D2;
    const float* N  = g_n2u + ((size_t)bi * NBATCH + s0) * D2;
    __shared__ float shW[64 * D2];
    __shared__ float shN[32 * 64];
    __shared__ float shInv[32];
    int t = threadIdx.x;
    if (t < 32) {
        int u = user[s0 + t];
        shInv[t] = 1.f / (ubd[u * NB + bi] + EPSF);
    }
    int cg = t & 31, sg = t >> 5;
    float acc[4][4];
    #pragma unroll
    for (int i = 0; i < 4; i++)
        #pragma unroll
        for (int j = 0; j < 4; j++) acc[i][j] = 0.f;
    for (int kp = 0; kp < 2; kp++) {
        __syncthreads();
        for (int p = t; p < 64 * D2; p += 256) shW[p] = Wb[kp * 64 * D2 + p];
        for (int p = t; p < 32 * 64; p += 256)
            shN[p] = N[(size_t)(p >> 6) * D2 + kp * 64 + (p & 63)];
        __syncthreads();
        for (int k = 0; k < 64; k++) {
            float4 w = ((const float4*)(shW + k * D2))[cg];
            #pragma unroll
            for (int i = 0; i < 4; i++) {
                float a = shN[(sg * 4 + i) * 64 + k];
                acc[i][0] += a * w.x; acc[i][1] += a * w.y;
                acc[i][2] += a * w.z; acc[i][3] += a * w.w;
            }
        }
    }
    float* O = g_i2u + ((size_t)bi * NBATCH + s0) * D2;
    #pragma unroll
    for (int i = 0; i < 4; i++) {
        float inv = shInv[sg * 4 + i];
        float4 o = {acc[i][0] * inv, acc[i][1] * inv, acc[i][2] * inv, acc[i][3] * inv};
        ((float4*)(O + (size_t)(sg * 4 + i) * D2))[cg] = o;
    }
}

__global__ void k_itf(const float* __restrict__ iemb, const float* __restrict__ W,
                      const float* __restrict__ itemW) {
    __shared__ float shM[D_N * D2];
    __shared__ float shA[32 * D_N];
    int t = threadIdx.x;
    for (int p = t; p < D_N * D2; p += 256) {
        int k = p >> 7, j = p & 127;
        float m = itemW[p];
        if (j >= D_N) m += W[k * D_N + (j - D_N)];
        shM[p] = m;
    }
    int r0 = blockIdx.x * 32;
    for (int p = t; p < 32 * D_N; p += 256) {
        int rr = p >> 6, cc = p & 63;
        int row = r0 + rr;
        shA[p] = (row < I_N) ? g_if[(size_t)row * D_N + cc] : 0.f;
    }
    __syncthreads();
    int cg = t & 31, sg = t >> 5;
    float acc[4][4];
    #pragma unroll
    for (int i = 0; i < 4; i++)
        #pragma unroll
        for (int j = 0; j < 4; j++) acc[i][j] = 0.f;
    for (int k = 0; k < D_N; k++) {
        float4 w = ((const float4*)(shM + k * D2))[cg];
        #pragma unroll
        for (int i = 0; i < 4; i++) {
            float a = shA[(sg * 4 + i) * D_N + k];
            acc[i][0] += a * w.x; acc[i][1] += a * w.y;
            acc[i][2] += a * w.z; acc[i][3] += a * w.w;
        }
    }
    #pragma unroll
    for (int i = 0; i < 4; i++) {
        int row = r0 + sg * 4 + i;
        if (row >= I_N) continue;
        float4 v = {acc[i][0], acc[i][1], acc[i][2], acc[i][3]};
        if (cg < 16) {
            float4 e = ((const float4*)(iemb + (size_t)row * D_N))[cg];
            v.x += e.x; v.y += e.y; v.z += e.z; v.w += e.w;
        }
        ((float4*)(g_itf + (size_t)row * D2))[cg] = v;
        float n = v.x * v.x + v.y * v.y + v.z * v.z + v.w * v.w;
        #pragma unroll
        for (int o = 16; o; o >>= 1) n += __shfl_xor_sync(0xffffffffu, n, o);
        if ((t & 31) == 0) g_itfn[row] = n;
    }
}

// uf from raw n2u (ufeat fused): f[t<64] = sum_bi (d*w/tw)/(d+eps) * n2u_raw
__global__ void k_uf(const float* __restrict__ uemb, const float* __restrict__ W,
                     const float* __restrict__ userW, const float* __restrict__ sigW,
                     const int* __restrict__ user, const float* __restrict__ ubd,
                     const float* __restrict__ bw) {
    int b = blockIdx.x;
    int u = user[b];
    if (g_u2slot[u] != b) return;
    int t = threadIdx.x;   // 128
    __shared__ float f[D_N];
    if (t < D_N) {
        float d0 = ubd[u * NB + 0], d1 = ubd[u * NB + 1], d2 = ubd[u * NB + 2];
        float w0 = bw[0], w1 = bw[1], w2 = bw[2];
        float tw = d0 * w0 + d1 * w1 + d2 * w2 + EPSF;
        float dd[NB] = {d0, d1, d2}, ww[NB] = {w0, w1, w2};
        float acc = 0.f;
        #pragma unroll
        for (int bi = 0; bi < NB; bi++) {
            float coef = (dd[bi] * ww[bi] / tw) / (dd[bi] + EPSF);
            acc += coef * g_n2u[((size_t)bi * NBATCH + b) * D2 + t];
        }
        f[t] = acc;
    }
    __syncthreads();
    float acc = 0.f;
    #pragma unroll
    for (int k = 0; k < D_N; k++) acc += f[k] * userW[k * D2 + t];
    if (t >= D_N) {
        #pragma unroll
        for (int k = 0; k < D_N; k++) acc += f[k] * W[k * D_N + (t - D_N)];
    } else {
        acc += uemb[(size_t)u * D_N + t];
    }
    g_uf[(size_t)b * D2 + t] = acc;

    float s1 = acc * sigW[t];
    float s2 = acc * acc;
    #pragma unroll
    for (int o = 16; o; o >>= 1) {
        s1 += __shfl_xor_sync(0xffffffffu, s1, o);
        s2 += __shfl_xor_sync(0xffffffffu, s2, o);
    }
    __shared__ float r1[4], r2[4];
    int wid = t >> 5;
    if ((t & 31) == 0) { r1[wid] = s1; r2[wid] = s2; }
    __syncthreads();
    if (t == 0) {
        g_sw[b]  = r1[0] + r1[1] + r1[2] + r1[3];
        g_ufn[b] = r2[0] + r2[1] + r2[2] + r2[3];
    }
}

// fused score2 + score1 + gate + L2
__global__ void k_scorefinal(const float* __restrict__ iemb, const int* __restrict__ user,
                             const int* __restrict__ item, float* __restrict__ out,
                             int out_size) {
    int w = (blockIdx.x * blockDim.x + threadIdx.x) >> 5;
    int lane = threadIdx.x & 31;
    int wlocal = threadIdx.x >> 5;
    __shared__ float l2s[8];
    float l2c = 0.f;
    if (w < NBATCH * NK) {
        int b = w / NK;
        int it = item[w];
        int r = g_u2slot[user[b]];
        float s2 = 0.f;
        #pragma unroll
        for (int bi = 0; bi < NB; bi++) {
            float4 a = ((const float4*)(g_i2u + ((size_t)bi * NBATCH + r) * D2))[lane];
            float4 v = (lane < 16)
                ? ((const float4*)(iemb + (size_t)it * D_N))[lane]
                : ((const float4*)(g_ii + (size_t)(bi * I_N + it) * D_N))[lane - 16];
            s2 += a.x * v.x + a.y * v.y + a.z * v.z + a.w * v.w;
        }
        float4 ua = ((const float4*)(g_uf  + (size_t)r  * D2))[lane];
        float4 iv = ((const float4*)(g_itf + (size_t)it * D2))[lane];
        float s1 = ua.x * iv.x + ua.y * iv.y + ua.z * iv.z + ua.w * iv.w;
        #pragma unroll
        for (int o = 16; o; o >>= 1) {
            s1 += __shfl_xor_sync(0xffffffffu, s1, o);
            s2 += __shfl_xor_sync(0xffffffffu, s2, o);
        }
        if (lane == 0) {
            float g = 1.f / (1.f + expf(-g_sw[r]));
            out[w] = s1 * g + (s2 * (1.f / 3.f)) * (1.f - g);
            l2c = REGF * (g_ufn[r] + g_itfn[it]);
        }
    }
    if (lane == 0) l2s[wlocal] = l2c;
    __syncthreads();
    if (threadIdx.x == 0 && out_size > NBATCH * NK) {
        float t = 0.f;
        #pragma unroll
        for (int i = 0; i < 8; i++) t += l2s[i];
        atomicAdd(&out[NBATCH * NK], t);
    }
}

// ---------------- launch ---------------------------------------------------
extern "C" void kernel_launch(void* const* d_in, const int* in_sizes, int n_in,
                              void* d_out, int out_size) {
    const float* user_emb = (const float*)d_in[0];
    const float* item_emb = (const float*)d_in[1];
    const float* ubd      = (const float*)d_in[2];
    const float* bw       = (const float*)d_in[3];
    const float* ig_deg   = (const float*)d_in[4];
    const float* ibW      = (const float*)d_in[5];
    const float* ipW      = (const float*)d_in[6];
    const float* W        = (const float*)d_in[7];
    const float* userW    = (const float*)d_in[8];
    const float* itemW    = (const float*)d_in[9];
    const float* sigW     = (const float*)d_in[10];
    const int*   ui_rows  = (const int*)d_in[11];
    const int*   ui_cols  = (const int*)d_in[12];
    const int*   ig_rows  = (const int*)d_in[13];
    const int*   ig_cols  = (const int*)d_in[14];
    const int*   trows    = (const int*)d_in[15];
    const int*   tcols    = (const int*)d_in[16];
    const int*   user     = (const int*)d_in[17];
    const int*   item     = (const int*)d_in[18];
    float* out = (float*)d_out;

    // One-time symbol addresses (first call = non-capturing correctness run).
    static void *p_u2slot = nullptr, *p_n2u, *p_cnt;
    if (p_u2slot == nullptr) {
        cudaGetSymbolAddress(&p_u2slot, g_u2slot);
        cudaGetSymbolAddress(&p_n2u,    g_n2u);
        cudaGetSymbolAddress(&p_cnt,    g_cnt);
    }

    // single stream, dependency-ordered (graph replay is effectively serial;
    // minimize total node time, not choreography)
    cudaMemsetAsync(p_cnt, 0, (CNT_N + 1) * sizeof(int), 0);
    cudaMemsetAsync(p_u2slot, 0x7f, U_N * sizeof(int), 0);
    cudaMemsetAsync(p_n2u, 0, NB * NBATCH * D2 * sizeof(float), 0);

    k_scatter<<<(NBATCH + 255) / 256, 256>>>(user, out, out_size);
    k_w1a<<<dim3(4, NB), 256>>>(ibW, ipW);
    k_w1b<<<dim3(4, NB), 256>>>(ipW);
    k_fillb<<<(NE_ALL / 8 + 255) / 256, 256>>>(ig_rows, ig_cols, trows, tcols);
    k_filter<<<(NB * NE_UI / 4 + 255) / 256, 256>>>(ui_rows, ui_cols);
    k_gather<<<(CNT_N * 32) / 256, 256>>>(item_emb, user_emb, ig_deg);
    k_ui_accum<<<512, 256>>>(item_emb);
    k_i2u<<<dim3(NBATCH / 32, NB), 256>>>(ubd, user);
    k_uf<<<NBATCH, 128>>>(user_emb, W, userW, sigW, user, ubd, bw);
    k_itf<<<(I_N + 31) / 32, 256>>>(item_emb, W, itemW);
    k_scorefinal<<<(NBATCH * NK * 32 + 255) / 256, 256>>>(item_emb, user, item,
                                                          out, out_size);
}

// round 13
// speedup vs baseline: 1.1314x; 1.1314x over previous
#include <cuda_runtime.h>

#define U_N    100000
#define I_N    30000
#define NB     3
#define D_N    64
#define D2     128
#define NE_UI  500000
#define NE_IG  400000
#define NE_TR  1000000
#define NE_ALL (NB * NE_IG + NE_TR)
#define NBATCH 2048
#define NK     20
#define BK     128
#define CNT_N  ((NB + 1) * I_N)
#define EPSF   1e-8f
#define REGF   1e-4f

// ---------------- scratch (device globals; no allocation) ------------------
__device__ __align__(16) float g_ii   [NB * I_N * D_N];   // (A_ii@item_emb)/deg
__device__ __align__(16) float g_if   [I_N * D_N];        // train^T @ user_emb
__device__ __align__(16) float g_itf  [I_N * D2];
__device__               float g_itfn [I_N];
__device__               int   g_u2slot[U_N];
__device__ __align__(16) float g_n2u  [NB * NBATCH * D2]; // RAW [A|B] accumulation
__device__ __align__(16) float g_i2u  [NB * NBATCH * D2]; // (n2u@W2)*inv_denom
__device__ __align__(16) float g_uf   [NBATCH * D2];
__device__               float g_sw   [NBATCH];
__device__               float g_ufn  [NBATCH];
__device__ __align__(16) float g_W1   [NB * D2 * D2];     // [ibW_top ; Wp@ibW_bot]
__device__ __align__(16) float g_W2   [NB * D2 * D2];     // + output-side Wp fold
// bucketed adjacency: rows 0..3*I_N-1 = ig behaviors, rows 3*I_N.. = train
__device__               int   g_cnt  [CNT_N + 1];        // +1: nhit counter
__device__               int   g_bkt  [(size_t)CNT_N * BK];
__device__               int   g_hit  [NB * NE_UI];

__device__ __forceinline__ void red_add4(float* p, float4 v) {
#if defined(__CUDA_ARCH__) && (__CUDA_ARCH__ >= 900)
    asm volatile("red.global.add.v4.f32 [%0], {%1,%2,%3,%4};"
                 :: "l"(p), "f"(v.x), "f"(v.y), "f"(v.z), "f"(v.w) : "memory");
#else
    atomicAdd(p + 0, v.x); atomicAdd(p + 1, v.y);
    atomicAdd(p + 2, v.z); atomicAdd(p + 3, v.w);
#endif
}

// ---------------- kernels --------------------------------------------------

// W1[:, c0..c0+32): top rows = ibW copy, bottom rows = Wp @ ibW_bot (smem GEMM)
__global__ void k_w1a(const float* __restrict__ ibW, const float* __restrict__ ipW) {
    int bi = blockIdx.y;
    int c0 = blockIdx.x * 32;
    const float* ibWb = ibW + (size_t)bi * D2 * D2;
    const float* wp   = ipW + (size_t)bi * D_N * D_N;
    __shared__ float shWpT[64 * 64];   // WpT[k][r] = Wp[r][k]
    __shared__ float shB[64 * 32];     // ibW_bot[k][c0+c]
    int t = threadIdx.x;               // 256
    for (int p = t; p < 64 * 64; p += 256) {
        int r = p >> 6, k = p & 63;
        shWpT[k * 64 + r] = wp[p];
    }
    for (int p = t; p < 64 * 32; p += 256) {
        int k = p >> 5, c = p & 31;
        shB[p] = ibWb[(size_t)(64 + k) * D2 + c0 + c];
    }
    __syncthreads();
    float* W1b = g_W1 + (size_t)bi * D2 * D2;
    for (int p = t; p < 64 * 32; p += 256) {
        int r = p >> 5, c = p & 31;
        W1b[r * D2 + c0 + c] = ibWb[r * D2 + c0 + c];
    }
    int r = t & 63, cq = (t >> 6) * 8;
    float acc[8];
    #pragma unroll
    for (int j = 0; j < 8; j++) acc[j] = 0.f;
    for (int k = 0; k < 64; k++) {
        float w = shWpT[k * 64 + r];
        #pragma unroll
        for (int j = 0; j < 8; j++) acc[j] += w * shB[k * 32 + cq + j];
    }
    #pragma unroll
    for (int j = 0; j < 8; j++)
        W1b[(64 + r) * D2 + c0 + cq + j] = acc[j];
}

// W2[:, c0..c0+32): cols<64 copy of W1; cols>=64: W1[:,64:] @ Wp^T (smem GEMM)
__global__ void k_w1b(const float* __restrict__ ipW) {
    int bi = blockIdx.y;
    int c0 = blockIdx.x * 32;
    const float* W1b = g_W1 + (size_t)bi * D2 * D2;
    float* W2b = g_W2 + (size_t)bi * D2 * D2;
    int t = threadIdx.x;               // 256
    if (c0 < 64) {
        for (int p = t; p < D2 * 32; p += 256) {
            int k = p >> 5, c = p & 31;
            W2b[k * D2 + c0 + c] = W1b[k * D2 + c0 + c];
        }
        return;
    }
    int r0 = c0 - 64;
    const float* wp = ipW + (size_t)bi * D_N * D_N;
    __shared__ float shW1rT[64 * D2];  // [j][k] = W1[k][64+j]
    __shared__ float shWpT [64 * 32];  // [j][r-r0] = Wp[r][j]
    for (int p = t; p < 64 * D2; p += 256) {
        int j = p >> 7, k = p & 127;
        shW1rT[j * D2 + k] = W1b[k * D2 + 64 + j];
    }
    for (int p = t; p < 64 * 32; p += 256) {
        int j = p >> 5, r = p & 31;
        shWpT[p] = wp[(r0 + r) * D_N + j];
    }
    __syncthreads();
    int k = t & 127, rq = (t >> 7) * 16;
    float acc[16];
    #pragma unroll
    for (int q = 0; q < 16; q++) acc[q] = 0.f;
    for (int j = 0; j < 64; j++) {
        float w1v = shW1rT[j * D2 + k];
        #pragma unroll
        for (int q = 0; q < 16; q++) acc[q] += w1v * shWpT[j * 32 + rq + q];
    }
    #pragma unroll
    for (int q = 0; q < 16; q++)
        W2b[k * D2 + 64 + r0 + rq + q] = acc[q];
}

__global__ void k_scatter(const int* __restrict__ user, float* out, int out_size) {
    int b = blockIdx.x * blockDim.x + threadIdx.x;
    if (b < NBATCH) atomicMin(&g_u2slot[user[b]], b);
    if (b == 0 && out_size > NBATCH * NK) out[NBATCH * NK] = 0.f;
}

// fused bucket fill, 8 edges/thread (8 independent atomic chains)
__global__ void k_fillb(const int* __restrict__ ig_rows, const int* __restrict__ ig_cols,
                        const int* __restrict__ trows, const int* __restrict__ tcols) {
    int i = (blockIdx.x * blockDim.x + threadIdx.x) * 8;
    if (i >= NE_ALL) return;
    const int *rbase, *cbase;
    int base;
    if (i < NB * NE_IG) {              // NE_IG % 8 == 0: uniform behavior per group
        rbase = ig_rows + i; cbase = ig_cols + i;
        base = (i / NE_IG) * I_N;
    } else {
        int j = i - NB * NE_IG;
        rbase = tcols + j; cbase = trows + j;   // dest=item, src=user
        base = NB * I_N;
    }
    int4 ra = ((const int4*)rbase)[0], rb = ((const int4*)rbase)[1];
    int4 ca = ((const int4*)cbase)[0], cb = ((const int4*)cbase)[1];
    int rr[8] = {ra.x, ra.y, ra.z, ra.w, rb.x, rb.y, rb.z, rb.w};
    int cc[8] = {ca.x, ca.y, ca.z, ca.w, cb.x, cb.y, cb.z, cb.w};
    #pragma unroll
    for (int j = 0; j < 8; j++) {
        int row = base + rr[j];
        int slot = atomicAdd(&g_cnt[row], 1);
        if (slot < BK) g_bkt[(size_t)row * BK + slot] = cc[j];
    }
}

// fused warp-per-row gather (ig rows -> g_ii, train rows -> g_if)
__global__ void k_gather(const float* __restrict__ iemb, const float* __restrict__ uemb,
                         const float* __restrict__ deg) {
    int w = (blockIdx.x * blockDim.x + threadIdx.x) >> 5;
    int lane = threadIdx.x & 31;
    if (w >= CNT_N) return;
    int bi = w / I_N, r = w - bi * I_N;
    int cnt = g_cnt[w]; if (cnt > BK) cnt = BK;
    const int* src = g_bkt + (size_t)w * BK;
    const float* emb = (bi < NB) ? iemb : uemb;
    float2 a0 = {0.f, 0.f}, a1 = {0.f, 0.f}, a2 = {0.f, 0.f}, a3 = {0.f, 0.f};
    for (int j = 0; j < cnt; j += 32) {
        int m = cnt - j; if (m > 32) m = 32;
        int sidx = (lane < m) ? src[j + lane] : 0;
        int q = 0;
        for (; q + 4 <= m; q += 4) {
            int s0 = __shfl_sync(0xffffffffu, sidx, q);
            int s1 = __shfl_sync(0xffffffffu, sidx, q + 1);
            int s2 = __shfl_sync(0xffffffffu, sidx, q + 2);
            int s3 = __shfl_sync(0xffffffffu, sidx, q + 3);
            float2 v0 = ((const float2*)(emb + (size_t)s0 * D_N))[lane];
            float2 v1 = ((const float2*)(emb + (size_t)s1 * D_N))[lane];
            float2 v2 = ((const float2*)(emb + (size_t)s2 * D_N))[lane];
            float2 v3 = ((const float2*)(emb + (size_t)s3 * D_N))[lane];
            a0.x += v0.x; a0.y += v0.y;  a1.x += v1.x; a1.y += v1.y;
            a2.x += v2.x; a2.y += v2.y;  a3.x += v3.x; a3.y += v3.y;
        }
        for (; q < m; q++) {
            int s = __shfl_sync(0xffffffffu, sidx, q);
            float2 v = ((const float2*)(emb + (size_t)s * D_N))[lane];
            a0.x += v.x; a0.y += v.y;
        }
    }
    float2 acc = {a0.x + a1.x + a2.x + a3.x, a0.y + a1.y + a2.y + a3.y};
    if (bi < NB) {
        float inv = 1.f / (deg[w] + EPSF);   // deg laid out [NB][I_N] == w
        acc.x *= inv; acc.y *= inv;
        ((float2*)(g_ii + (size_t)w * D_N))[lane] = acc;
    } else {
        ((float2*)(g_if + (size_t)r * D_N))[lane] = acc;
    }
}

// scan ui edges, compact hits (slot,col) keys (warp-aggregated append)
__global__ void k_filter(const int* __restrict__ rows, const int* __restrict__ cols) {
    int i = (blockIdx.x * blockDim.x + threadIdx.x) * 4;
    int lane = threadIdx.x & 31;
    bool in = (i < NB * NE_UI);
    int4 r = in ? *(const int4*)(rows + i) : make_int4(0, 0, 0, 0);
    int bi = in ? (i / NE_UI) : 0;
    int rb = bi * NBATCH;
    int rr[4] = {r.x, r.y, r.z, r.w};
    #pragma unroll
    for (int j = 0; j < 4; j++) {
        int sl = in ? g_u2slot[rr[j]] : 0x7fffffff;
        bool hit = sl < NBATCH;
        unsigned m = __ballot_sync(0xffffffffu, hit);
        if (m) {
            int leader = __ffs(m) - 1;
            int base;
            if (lane == leader) base = atomicAdd(&g_cnt[CNT_N], __popc(m));
            base = __shfl_sync(0xffffffffu, base, leader);
            if (hit) {
                int col = cols[i + j];
                g_hit[base + __popc(m & ((1u << lane) - 1))] = ((rb + sl) << 15) | col;
            }
        }
    }
}

// accumulate hit edges: n2u[rs] += [item_emb[col] | g_ii[bi][col]]  (RAW)
__global__ void k_ui_accum(const float* __restrict__ iemb) {
    int nw = (gridDim.x * blockDim.x) >> 5;
    int w = (blockIdx.x * blockDim.x + threadIdx.x) >> 5;
    int lane = threadIdx.x & 31;
    int n = g_cnt[CNT_N];
    for (int h = w; h < n; h += nw) {
        int key = g_hit[h];
        int col = key & 0x7fff;
        int rs = key >> 15;
        int bi = rs >> 11;
        float* base = g_n2u + (size_t)rs * D2;
        float4 v;
        float* dst;
        if (lane < 16) {
            v = ((const float4*)(iemb + (size_t)col * D_N))[lane];
            dst = base + lane * 4;
        } else {
            v = ((const float4*)(g_ii + (size_t)(bi * I_N + col) * D_N))[lane - 16];
            dst = base + 64 + (lane - 16) * 4;
        }
        red_add4(dst, v);
    }
}

// i2u[bi][s] = (raw_n2u[bi][s] @ W2[bi]) * inv_denom[bi][s]   (norm fused)
__global__ void k_i2u(const float* __restrict__ ubd, const int* __restrict__ user) {
    int bi = blockIdx.y;
    int s0 = blockIdx.x * 32;
    const float* Wb = g_W2 + (size_t)bi * D2 * D2;
    const float* N  = g_n2u + ((size_t)bi * NBATCH + s0) * D2;
    __shared__ float shW[64 * D2];
    __shared__ float shN[32 * 64];
    __shared__ float shInv[32];
    int t = threadIdx.x;
    if (t < 32) {
        int u = user[s0 + t];
        shInv[t] = 1.f / (ubd[u * NB + bi] + EPSF);
    }
    int cg = t & 31, sg = t >> 5;
    float acc[4][4];
    #pragma unroll
    for (int i = 0; i < 4; i++)
        #pragma unroll
        for (int j = 0; j < 4; j++) acc[i][j] = 0.f;
    for (int kp = 0; kp < 2; kp++) {
        __syncthreads();
        for (int p = t; p < 64 * D2; p += 256) shW[p] = Wb[kp * 64 * D2 + p];
        for (int p = t; p < 32 * 64; p += 256)
            shN[p] = N[(size_t)(p >> 6) * D2 + kp * 64 + (p & 63)];
        __syncthreads();
        for (int k = 0; k < 64; k++) {
            float4 w = ((const float4*)(shW + k * D2))[cg];
            #pragma unroll
            for (int i = 0; i < 4; i++) {
                float a = shN[(sg * 4 + i) * 64 + k];
                acc[i][0] += a * w.x; acc[i][1] += a * w.y;
                acc[i][2] += a * w.z; acc[i][3] += a * w.w;
            }
        }
    }
    float* O = g_i2u + ((size_t)bi * NBATCH + s0) * D2;
    #pragma unroll
    for (int i = 0; i < 4; i++) {
        float inv = shInv[sg * 4 + i];
        float4 o = {acc[i][0] * inv, acc[i][1] * inv, acc[i][2] * inv, acc[i][3] * inv};
        ((float4*)(O + (size_t)(sg * 4 + i) * D2))[cg] = o;
    }
}

__global__ void k_itf(const float* __restrict__ iemb, const float* __restrict__ W,
                      const float* __restrict__ itemW) {
    __shared__ float shM[D_N * D2];
    __shared__ float shA[32 * D_N];
    int t = threadIdx.x;
    for (int p = t; p < D_N * D2; p += 256) {
        int k = p >> 7, j = p & 127;
        float m = itemW[p];
        if (j >= D_N) m += W[k * D_N + (j - D_N)];
        shM[p] = m;
    }
    int r0 = blockIdx.x * 32;
    for (int p = t; p < 32 * D_N; p += 256) {
        int rr = p >> 6, cc = p & 63;
        int row = r0 + rr;
        shA[p] = (row < I_N) ? g_if[(size_t)row * D_N + cc] : 0.f;
    }
    __syncthreads();
    int cg = t & 31, sg = t >> 5;
    float acc[4][4];
    #pragma unroll
    for (int i = 0; i < 4; i++)
        #pragma unroll
        for (int j = 0; j < 4; j++) acc[i][j] = 0.f;
    for (int k = 0; k < D_N; k++) {
        float4 w = ((const float4*)(shM + k * D2))[cg];
        #pragma unroll
        for (int i = 0; i < 4; i++) {
            float a = shA[(sg * 4 + i) * D_N + k];
            acc[i][0] += a * w.x; acc[i][1] += a * w.y;
            acc[i][2] += a * w.z; acc[i][3] += a * w.w;
        }
    }
    #pragma unroll
    for (int i = 0; i < 4; i++) {
        int row = r0 + sg * 4 + i;
        if (row >= I_N) continue;
        float4 v = {acc[i][0], acc[i][1], acc[i][2], acc[i][3]};
        if (cg < 16) {
            float4 e = ((const float4*)(iemb + (size_t)row * D_N))[cg];
            v.x += e.x; v.y += e.y; v.z += e.z; v.w += e.w;
        }
        ((float4*)(g_itf + (size_t)row * D2))[cg] = v;
        float n = v.x * v.x + v.y * v.y + v.z * v.z + v.w * v.w;
        #pragma unroll
        for (int o = 16; o; o >>= 1) n += __shfl_xor_sync(0xffffffffu, n, o);
        if ((t & 31) == 0) g_itfn[row] = n;
    }
}

// uf from raw n2u (ufeat fused): f[t<64] = sum_bi (d*w/tw)/(d+eps) * n2u_raw
__global__ void k_uf(const float* __restrict__ uemb, const float* __restrict__ W,
                     const float* __restrict__ userW, const float* __restrict__ sigW,
                     const int* __restrict__ user, const float* __restrict__ ubd,
                     const float* __restrict__ bw) {
    int b = blockIdx.x;
    int u = user[b];
    if (g_u2slot[u] != b) return;
    int t = threadIdx.x;   // 128
    __shared__ float f[D_N];
    if (t < D_N) {
        float d0 = ubd[u * NB + 0], d1 = ubd[u * NB + 1], d2 = ubd[u * NB + 2];
        float w0 = bw[0], w1 = bw[1], w2 = bw[2];
        float tw = d0 * w0 + d1 * w1 + d2 * w2 + EPSF;
        float dd[NB] = {d0, d1, d2}, ww[NB] = {w0, w1, w2};
        float acc = 0.f;
        #pragma unroll
        for (int bi = 0; bi < NB; bi++) {
            float coef = (dd[bi] * ww[bi] / tw) / (dd[bi] + EPSF);
            acc += coef * g_n2u[((size_t)bi * NBATCH + b) * D2 + t];
        }
        f[t] = acc;
    }
    __syncthreads();
    float acc = 0.f;
    #pragma unroll
    for (int k = 0; k < D_N; k++) acc += f[k] * userW[k * D2 + t];
    if (t >= D_N) {
        #pragma unroll
        for (int k = 0; k < D_N; k++) acc += f[k] * W[k * D_N + (t - D_N)];
    } else {
        acc += uemb[(size_t)u * D_N + t];
    }
    g_uf[(size_t)b * D2 + t] = acc;

    float s1 = acc * sigW[t];
    float s2 = acc * acc;
    #pragma unroll
    for (int o = 16; o; o >>= 1) {
        s1 += __shfl_xor_sync(0xffffffffu, s1, o);
        s2 += __shfl_xor_sync(0xffffffffu, s2, o);
    }
    __shared__ float r1[4], r2[4];
    int wid = t >> 5;
    if ((t & 31) == 0) { r1[wid] = s1; r2[wid] = s2; }
    __syncthreads();
    if (t == 0) {
        g_sw[b]  = r1[0] + r1[1] + r1[2] + r1[3];
        g_ufn[b] = r2[0] + r2[1] + r2[2] + r2[3];
    }
}

// fused score2 + score1 + gate + L2
__global__ void k_scorefinal(const float* __restrict__ iemb, const int* __restrict__ user,
                             const int* __restrict__ item, float* __restrict__ out,
                             int out_size) {
    int w = (blockIdx.x * blockDim.x + threadIdx.x) >> 5;
    int lane = threadIdx.x & 31;
    int wlocal = threadIdx.x >> 5;
    __shared__ float l2s[8];
    float l2c = 0.f;
    if (w < NBATCH * NK) {
        int b = w / NK;
        int it = item[w];
        int r = g_u2slot[user[b]];
        float s2 = 0.f;
        #pragma unroll
        for (int bi = 0; bi < NB; bi++) {
            float4 a = ((const float4*)(g_i2u + ((size_t)bi * NBATCH + r) * D2))[lane];
            float4 v = (lane < 16)
                ? ((const float4*)(iemb + (size_t)it * D_N))[lane]
                : ((const float4*)(g_ii + (size_t)(bi * I_N + it) * D_N))[lane - 16];
            s2 += a.x * v.x + a.y * v.y + a.z * v.z + a.w * v.w;
        }
        float4 ua = ((const float4*)(g_uf  + (size_t)r  * D2))[lane];
        float4 iv = ((const float4*)(g_itf + (size_t)it * D2))[lane];
        float s1 = ua.x * iv.x + ua.y * iv.y + ua.z * iv.z + ua.w * iv.w;
        #pragma unroll
        for (int o = 16; o; o >>= 1) {
            s1 += __shfl_xor_sync(0xffffffffu, s1, o);
            s2 += __shfl_xor_sync(0xffffffffu, s2, o);
        }
        if (lane == 0) {
            float g = 1.f / (1.f + expf(-g_sw[r]));
            out[w] = s1 * g + (s2 * (1.f / 3.f)) * (1.f - g);
            l2c = REGF * (g_ufn[r] + g_itfn[it]);
        }
    }
    if (lane == 0) l2s[wlocal] = l2c;
    __syncthreads();
    if (threadIdx.x == 0 && out_size > NBATCH * NK) {
        float t = 0.f;
        #pragma unroll
        for (int i = 0; i < 8; i++) t += l2s[i];
        atomicAdd(&out[NBATCH * NK], t);
    }
}

// ---------------- launch ---------------------------------------------------
extern "C" void kernel_launch(void* const* d_in, const int* in_sizes, int n_in,
                              void* d_out, int out_size) {
    const float* user_emb = (const float*)d_in[0];
    const float* item_emb = (const float*)d_in[1];
    const float* ubd      = (const float*)d_in[2];
    const float* bw       = (const float*)d_in[3];
    const float* ig_deg   = (const float*)d_in[4];
    const float* ibW      = (const float*)d_in[5];
    const float* ipW      = (const float*)d_in[6];
    const float* W        = (const float*)d_in[7];
    const float* userW    = (const float*)d_in[8];
    const float* itemW    = (const float*)d_in[9];
    const float* sigW     = (const float*)d_in[10];
    const int*   ui_rows  = (const int*)d_in[11];
    const int*   ui_cols  = (const int*)d_in[12];
    const int*   ig_rows  = (const int*)d_in[13];
    const int*   ig_cols  = (const int*)d_in[14];
    const int*   trows    = (const int*)d_in[15];
    const int*   tcols    = (const int*)d_in[16];
    const int*   user     = (const int*)d_in[17];
    const int*   item     = (const int*)d_in[18];
    float* out = (float*)d_out;

    // One-time handles + symbol addresses (first call = non-capturing
    // correctness run; capture call reuses — no resource-mgmt API in capture).
    static cudaStream_t s1 = nullptr, s2 = nullptr;
    static cudaEvent_t evC = nullptr, evG = nullptr, evT = nullptr;
    static void *p_u2slot, *p_n2u, *p_cnt;
    if (s1 == nullptr) {
        cudaStreamCreateWithFlags(&s1, cudaStreamNonBlocking);
        cudaStreamCreateWithFlags(&s2, cudaStreamNonBlocking);
        cudaEventCreateWithFlags(&evC, cudaEventDisableTiming);
        cudaEventCreateWithFlags(&evG, cudaEventDisableTiming);
        cudaEventCreateWithFlags(&evT, cudaEventDisableTiming);
        cudaGetSymbolAddress(&p_u2slot, g_u2slot);
        cudaGetSymbolAddress(&p_n2u,    g_n2u);
        cudaGetSymbolAddress(&p_cnt,    g_cnt);
    }

    // head: only the counter memset gates s1
    cudaMemsetAsync(p_cnt, 0, (CNT_N + 1) * sizeof(int), 0);
    cudaEventRecord(evC, 0);
    cudaStreamWaitEvent(s1, evC, 0);

    // ---- s1 (critical path): fused fill -> fused gather ----
    k_fillb<<<(NE_ALL / 8 + 255) / 256, 256, 0, s1>>>(ig_rows, ig_cols, trows, tcols);
    k_gather<<<(CNT_N * 32) / 256, 256, 0, s1>>>(item_emb, user_emb, ig_deg);
    cudaEventRecord(evG, s1);

    // ---- stream 0 (hidden under s1): inits, scatter, filter, weight folds ----
    cudaMemsetAsync(p_u2slot, 0x7f, U_N * sizeof(int), 0);        // "inf" slots
    cudaMemsetAsync(p_n2u, 0, NB * NBATCH * D2 * sizeof(float), 0);
    k_scatter<<<(NBATCH + 255) / 256, 256>>>(user, out, out_size);
    k_filter<<<(NB * NE_UI / 4 + 255) / 256, 256>>>(ui_rows, ui_cols);
    k_w1a<<<dim3(4, NB), 256>>>(ibW, ipW);
    k_w1b<<<dim3(4, NB), 256>>>(ipW);

    // ---- s2: itf (needs gather's g_if; concurrent with stream-0 tail) ----
    cudaStreamWaitEvent(s2, evG, 0);
    k_itf<<<(I_N + 31) / 32, 256, 0, s2>>>(item_emb, W, itemW);
    cudaEventRecord(evT, s2);

    // ---- stream 0 tail (needs g_ii / filter output) ----
    cudaStreamWaitEvent(0, evG, 0);
    k_ui_accum<<<512, 256>>>(item_emb);
    k_i2u<<<dim3(NBATCH / 32, NB), 256>>>(ubd, user);
    k_uf<<<NBATCH, 128>>>(user_emb, W, userW, sigW, user, ubd, bw);

    cudaStreamWaitEvent(0, evT, 0);
    k_scorefinal<<<(NBATCH * NK * 32 + 255) / 256, 256>>>(item_emb, user, item,
                                                          out, out_size);
}

// round 14
// speedup vs baseline: 1.1340x; 1.0023x over previous
#include <cuda_runtime.h>

#define U_N    100000
#define I_N    30000
#define NB     3
#define D_N    64
#define D2     128
#define NE_UI  500000
#define NE_IG  400000
#define NE_TR  1000000
#define NE_ALL (NB * NE_IG + NE_TR)
#define NBATCH 2048
#define NK     20
#define BK     128
#define CNT_N  ((NB + 1) * I_N)
#define EPSF   1e-8f
#define REGF   1e-4f

// ---------------- scratch (device globals; no allocation) ------------------
__device__ __align__(16) float g_ii   [NB * I_N * D_N];   // (A_ii@item_emb)/deg
__device__ __align__(16) float g_if   [I_N * D_N];        // train^T @ user_emb
__device__ __align__(16) float g_itf  [I_N * D2];
__device__               float g_itfn [I_N];
__device__               int   g_u2slot[U_N];
__device__ __align__(16) float g_n2u  [NB * NBATCH * D2]; // RAW [A|B] accumulation
__device__ __align__(16) float g_i2u  [NB * NBATCH * D2]; // (n2u@W2)*inv_denom
__device__ __align__(16) float g_uf   [NBATCH * D2];
__device__               float g_sw   [NBATCH];
__device__               float g_ufn  [NBATCH];
__device__ __align__(16) float g_W1   [NB * D2 * D2];     // [ibW_top ; Wp@ibW_bot]
__device__ __align__(16) float g_W2   [NB * D2 * D2];     // + output-side Wp fold
// bucketed adjacency: rows 0..3*I_N-1 = ig behaviors, rows 3*I_N.. = train
__device__               int   g_cnt  [CNT_N + 1];        // +1: nhit counter
__device__               int   g_bkt  [(size_t)CNT_N * BK];
__device__               int   g_hit  [NB * NE_UI];

__device__ __forceinline__ void red_add4(float* p, float4 v) {
#if defined(__CUDA_ARCH__) && (__CUDA_ARCH__ >= 900)
    asm volatile("red.global.add.v4.f32 [%0], {%1,%2,%3,%4};"
                 :: "l"(p), "f"(v.x), "f"(v.y), "f"(v.z), "f"(v.w) : "memory");
#else
    atomicAdd(p + 0, v.x); atomicAdd(p + 1, v.y);
    atomicAdd(p + 2, v.z); atomicAdd(p + 3, v.w);
#endif
}

// ---------------- kernels --------------------------------------------------

// fused init: n2u=0, u2slot=inf, cnt=0, out L2 slot=0  (replaces 3 memsets)
__global__ void k_init(float* out, int out_size) {
    int i = blockIdx.x * blockDim.x + threadIdx.x;
    if (i < NB * NBATCH * D2) g_n2u[i] = 0.f;
    if (i < U_N)              g_u2slot[i] = 0x7fffffff;
    if (i < CNT_N + 1)        g_cnt[i] = 0;
    if (i == 0 && out_size > NBATCH * NK) out[NBATCH * NK] = 0.f;
}

// W1[:, c0..c0+32): top rows = ibW copy, bottom rows = Wp @ ibW_bot (smem GEMM)
__global__ void k_w1a(const float* __restrict__ ibW, const float* __restrict__ ipW) {
    int bi = blockIdx.y;
    int c0 = blockIdx.x * 32;
    const float* ibWb = ibW + (size_t)bi * D2 * D2;
    const float* wp   = ipW + (size_t)bi * D_N * D_N;
    __shared__ float shWpT[64 * 64];   // WpT[k][r] = Wp[r][k]
    __shared__ float shB[64 * 32];     // ibW_bot[k][c0+c]
    int t = threadIdx.x;               // 256
    for (int p = t; p < 64 * 64; p += 256) {
        int r = p >> 6, k = p & 63;
        shWpT[k * 64 + r] = wp[p];
    }
    for (int p = t; p < 64 * 32; p += 256) {
        int k = p >> 5, c = p & 31;
        shB[p] = ibWb[(size_t)(64 + k) * D2 + c0 + c];
    }
    __syncthreads();
    float* W1b = g_W1 + (size_t)bi * D2 * D2;
    for (int p = t; p < 64 * 32; p += 256) {
        int r = p >> 5, c = p & 31;
        W1b[r * D2 + c0 + c] = ibWb[r * D2 + c0 + c];
    }
    int r = t & 63, cq = (t >> 6) * 8;
    float acc[8];
    #pragma unroll
    for (int j = 0; j < 8; j++) acc[j] = 0.f;
    for (int k = 0; k < 64; k++) {
        float w = shWpT[k * 64 + r];
        #pragma unroll
        for (int j = 0; j < 8; j++) acc[j] += w * shB[k * 32 + cq + j];
    }
    #pragma unroll
    for (int j = 0; j < 8; j++)
        W1b[(64 + r) * D2 + c0 + cq + j] = acc[j];
}

// W2[:, c0..c0+32): cols<64 copy of W1; cols>=64: W1[:,64:] @ Wp^T (smem GEMM)
__global__ void k_w1b(const float* __restrict__ ipW) {
    int bi = blockIdx.y;
    int c0 = blockIdx.x * 32;
    const float* W1b = g_W1 + (size_t)bi * D2 * D2;
    float* W2b = g_W2 + (size_t)bi * D2 * D2;
    int t = threadIdx.x;               // 256
    if (c0 < 64) {
        for (int p = t; p < D2 * 32; p += 256) {
            int k = p >> 5, c = p & 31;
            W2b[k * D2 + c0 + c] = W1b[k * D2 + c0 + c];
        }
        return;
    }
    int r0 = c0 - 64;
    const float* wp = ipW + (size_t)bi * D_N * D_N;
    __shared__ float shW1rT[64 * D2];  // [j][k] = W1[k][64+j]
    __shared__ float shWpT [64 * 32];  // [j][r-r0] = Wp[r][j]
    for (int p = t; p < 64 * D2; p += 256) {
        int j = p >> 7, k = p & 127;
        shW1rT[j * D2 + k] = W1b[k * D2 + 64 + j];
    }
    for (int p = t; p < 64 * 32; p += 256) {
        int j = p >> 5, r = p & 31;
        shWpT[p] = wp[(r0 + r) * D_N + j];
    }
    __syncthreads();
    int k = t & 127, rq = (t >> 7) * 16;
    float acc[16];
    #pragma unroll
    for (int q = 0; q < 16; q++) acc[q] = 0.f;
    for (int j = 0; j < 64; j++) {
        float w1v = shW1rT[j * D2 + k];
        #pragma unroll
        for (int q = 0; q < 16; q++) acc[q] += w1v * shWpT[j * 32 + rq + q];
    }
    #pragma unroll
    for (int q = 0; q < 16; q++)
        W2b[k * D2 + 64 + r0 + rq + q] = acc[q];
}

__global__ void k_scatter(const int* __restrict__ user) {
    int b = blockIdx.x * blockDim.x + threadIdx.x;
    if (b < NBATCH) atomicMin(&g_u2slot[user[b]], b);
}

// fused bucket fill, 8 edges/thread (8 independent atomic chains)
__global__ void k_fillb(const int* __restrict__ ig_rows, const int* __restrict__ ig_cols,
                        const int* __restrict__ trows, const int* __restrict__ tcols) {
    int i = (blockIdx.x * blockDim.x + threadIdx.x) * 8;
    if (i >= NE_ALL) return;
    const int *rbase, *cbase;
    int base;
    if (i < NB * NE_IG) {              // NE_IG % 8 == 0: uniform behavior per group
        rbase = ig_rows + i; cbase = ig_cols + i;
        base = (i / NE_IG) * I_N;
    } else {
        int j = i - NB * NE_IG;
        rbase = tcols + j; cbase = trows + j;   // dest=item, src=user
        base = NB * I_N;
    }
    int4 ra = ((const int4*)rbase)[0], rb = ((const int4*)rbase)[1];
    int4 ca = ((const int4*)cbase)[0], cb = ((const int4*)cbase)[1];
    int rr[8] = {ra.x, ra.y, ra.z, ra.w, rb.x, rb.y, rb.z, rb.w};
    int cc[8] = {ca.x, ca.y, ca.z, ca.w, cb.x, cb.y, cb.z, cb.w};
    #pragma unroll
    for (int j = 0; j < 8; j++) {
        int row = base + rr[j];
        int slot = atomicAdd(&g_cnt[row], 1);
        if (slot < BK) g_bkt[(size_t)row * BK + slot] = cc[j];
    }
}

// fused warp-per-row gather (ig rows -> g_ii, train rows -> g_if)
__global__ void k_gather(const float* __restrict__ iemb, const float* __restrict__ uemb,
                         const float* __restrict__ deg) {
    int w = (blockIdx.x * blockDim.x + threadIdx.x) >> 5;
    int lane = threadIdx.x & 31;
    if (w >= CNT_N) return;
    int bi = w / I_N, r = w - bi * I_N;
    int cnt = g_cnt[w]; if (cnt > BK) cnt = BK;
    const int* src = g_bkt + (size_t)w * BK;
    const float* emb = (bi < NB) ? iemb : uemb;
    float2 a0 = {0.f, 0.f}, a1 = {0.f, 0.f}, a2 = {0.f, 0.f}, a3 = {0.f, 0.f};
    for (int j = 0; j < cnt; j += 32) {
        int m = cnt - j; if (m > 32) m = 32;
        int sidx = (lane < m) ? src[j + lane] : 0;
        int q = 0;
        for (; q + 4 <= m; q += 4) {
            int s0 = __shfl_sync(0xffffffffu, sidx, q);
            int s1 = __shfl_sync(0xffffffffu, sidx, q + 1);
            int s2 = __shfl_sync(0xffffffffu, sidx, q + 2);
            int s3 = __shfl_sync(0xffffffffu, sidx, q + 3);
            float2 v0 = ((const float2*)(emb + (size_t)s0 * D_N))[lane];
            float2 v1 = ((const float2*)(emb + (size_t)s1 * D_N))[lane];
            float2 v2 = ((const float2*)(emb + (size_t)s2 * D_N))[lane];
            float2 v3 = ((const float2*)(emb + (size_t)s3 * D_N))[lane];
            a0.x += v0.x; a0.y += v0.y;  a1.x += v1.x; a1.y += v1.y;
            a2.x += v2.x; a2.y += v2.y;  a3.x += v3.x; a3.y += v3.y;
        }
        for (; q < m; q++) {
            int s = __shfl_sync(0xffffffffu, sidx, q);
            float2 v = ((const float2*)(emb + (size_t)s * D_N))[lane];
            a0.x += v.x; a0.y += v.y;
        }
    }
    float2 acc = {a0.x + a1.x + a2.x + a3.x, a0.y + a1.y + a2.y + a3.y};
    if (bi < NB) {
        float inv = 1.f / (deg[w] + EPSF);   // deg laid out [NB][I_N] == w
        acc.x *= inv; acc.y *= inv;
        ((float2*)(g_ii + (size_t)w * D_N))[lane] = acc;
    } else {
        ((float2*)(g_if + (size_t)r * D_N))[lane] = acc;
    }
}

// scan ui edges, compact hits (slot,col) keys (warp-aggregated append)
__global__ void k_filter(const int* __restrict__ rows, const int* __restrict__ cols) {
    int i = (blockIdx.x * blockDim.x + threadIdx.x) * 4;
    int lane = threadIdx.x & 31;
    bool in = (i < NB * NE_UI);
    int4 r = in ? *(const int4*)(rows + i) : make_int4(0, 0, 0, 0);
    int bi = in ? (i / NE_UI) : 0;
    int rb = bi * NBATCH;
    int rr[4] = {r.x, r.y, r.z, r.w};
    #pragma unroll
    for (int j = 0; j < 4; j++) {
        int sl = in ? g_u2slot[rr[j]] : 0x7fffffff;
        bool hit = sl < NBATCH;
        unsigned m = __ballot_sync(0xffffffffu, hit);
        if (m) {
            int leader = __ffs(m) - 1;
            int base;
            if (lane == leader) base = atomicAdd(&g_cnt[CNT_N], __popc(m));
            base = __shfl_sync(0xffffffffu, base, leader);
            if (hit) {
                int col = cols[i + j];
                g_hit[base + __popc(m & ((1u << lane) - 1))] = ((rb + sl) << 15) | col;
            }
        }
    }
}

// accumulate hit edges: n2u[rs] += [item_emb[col] | g_ii[bi][col]]  (RAW)
__global__ void k_ui_accum(const float* __restrict__ iemb) {
    int nw = (gridDim.x * blockDim.x) >> 5;
    int w = (blockIdx.x * blockDim.x + threadIdx.x) >> 5;
    int lane = threadIdx.x & 31;
    int n = g_cnt[CNT_N];
    for (int h = w; h < n; h += nw) {
        int key = g_hit[h];
        int col = key & 0x7fff;
        int rs = key >> 15;
        int bi = rs >> 11;
        float* base = g_n2u + (size_t)rs * D2;
        float4 v;
        float* dst;
        if (lane < 16) {
            v = ((const float4*)(iemb + (size_t)col * D_N))[lane];
            dst = base + lane * 4;
        } else {
            v = ((const float4*)(g_ii + (size_t)(bi * I_N + col) * D_N))[lane - 16];
            dst = base + 64 + (lane - 16) * 4;
        }
        red_add4(dst, v);
    }
}

// i2u[bi][s] = (raw_n2u[bi][s] @ W2[bi]) * inv_denom[bi][s]   (norm fused)
__global__ void k_i2u(const float* __restrict__ ubd, const int* __restrict__ user) {
    int bi = blockIdx.y;
    int s0 = blockIdx.x * 32;
    const float* Wb = g_W2 + (size_t)bi * D2 * D2;
    const float* N  = g_n2u + ((size_t)bi * NBATCH + s0) * D2;
    __shared__ float shW[64 * D2];
    __shared__ float shN[32 * 64];
    __shared__ float shInv[32];
    int t = threadIdx.x;
    if (t < 32) {
        int u = user[s0 + t];
        shInv[t] = 1.f / (ubd[u * NB + bi] + EPSF);
    }
    int cg = t & 31, sg = t >> 5;
    float acc[4][4];
    #pragma unroll
    for (int i = 0; i < 4; i++)
        #pragma unroll
        for (int j = 0; j < 4; j++) acc[i][j] = 0.f;
    for (int kp = 0; kp < 2; kp++) {
        __syncthreads();
        for (int p = t; p < 64 * D2; p += 256) shW[p] = Wb[kp * 64 * D2 + p];
        for (int p = t; p < 32 * 64; p += 256)
            shN[p] = N[(size_t)(p >> 6) * D2 + kp * 64 + (p & 63)];
        __syncthreads();
        for (int k = 0; k < 64; k++) {
            float4 w = ((const float4*)(shW + k * D2))[cg];
            #pragma unroll
            for (int i = 0; i < 4; i++) {
                float a = shN[(sg * 4 + i) * 64 + k];
                acc[i][0] += a * w.x; acc[i][1] += a * w.y;
                acc[i][2] += a * w.z; acc[i][3] += a * w.w;
            }
        }
    }
    float* O = g_i2u + ((size_t)bi * NBATCH + s0) * D2;
    #pragma unroll
    for (int i = 0; i < 4; i++) {
        float inv = shInv[sg * 4 + i];
        float4 o = {acc[i][0] * inv, acc[i][1] * inv, acc[i][2] * inv, acc[i][3] * inv};
        ((float4*)(O + (size_t)(sg * 4 + i) * D2))[cg] = o;
    }
}

__global__ void k_itf(const float* __restrict__ iemb, const float* __restrict__ W,
                      const float* __restrict__ itemW) {
    __shared__ float shM[D_N * D2];
    __shared__ float shA[32 * D_N];
    int t = threadIdx.x;
    for (int p = t; p < D_N * D2; p += 256) {
        int k = p >> 7, j = p & 127;
        float m = itemW[p];
        if (j >= D_N) m += W[k * D_N + (j - D_N)];
        shM[p] = m;
    }
    int r0 = blockIdx.x * 32;
    for (int p = t; p < 32 * D_N; p += 256) {
        int rr = p >> 6, cc = p & 63;
        int row = r0 + rr;
        shA[p] = (row < I_N) ? g_if[(size_t)row * D_N + cc] : 0.f;
    }
    __syncthreads();
    int cg = t & 31, sg = t >> 5;
    float acc[4][4];
    #pragma unroll
    for (int i = 0; i < 4; i++)
        #pragma unroll
        for (int j = 0; j < 4; j++) acc[i][j] = 0.f;
    for (int k = 0; k < D_N; k++) {
        float4 w = ((const float4*)(shM + k * D2))[cg];
        #pragma unroll
        for (int i = 0; i < 4; i++) {
            float a = shA[(sg * 4 + i) * D_N + k];
            acc[i][0] += a * w.x; acc[i][1] += a * w.y;
            acc[i][2] += a * w.z; acc[i][3] += a * w.w;
        }
    }
    #pragma unroll
    for (int i = 0; i < 4; i++) {
        int row = r0 + sg * 4 + i;
        if (row >= I_N) continue;
        float4 v = {acc[i][0], acc[i][1], acc[i][2], acc[i][3]};
        if (cg < 16) {
            float4 e = ((const float4*)(iemb + (size_t)row * D_N))[cg];
            v.x += e.x; v.y += e.y; v.z += e.z; v.w += e.w;
        }
        ((float4*)(g_itf + (size_t)row * D2))[cg] = v;
        float n = v.x * v.x + v.y * v.y + v.z * v.z + v.w * v.w;
        #pragma unroll
        for (int o = 16; o; o >>= 1) n += __shfl_xor_sync(0xffffffffu, n, o);
        if ((t & 31) == 0) g_itfn[row] = n;
    }
}

// uf from raw n2u (ufeat fused): f[t<64] = sum_bi (d*w/tw)/(d+eps) * n2u_raw
__global__ void k_uf(const float* __restrict__ uemb, const float* __restrict__ W,
                     const float* __restrict__ userW, const float* __restrict__ sigW,
                     const int* __restrict__ user, const float* __restrict__ ubd,
                     const float* __restrict__ bw) {
    int b = blockIdx.x;
    int u = user[b];
    if (g_u2slot[u] != b) return;
    int t = threadIdx.x;   // 128
    __shared__ float f[D_N];
    if (t < D_N) {
        float d0 = ubd[u * NB + 0], d1 = ubd[u * NB + 1], d2 = ubd[u * NB + 2];
        float w0 = bw[0], w1 = bw[1], w2 = bw[2];
        float tw = d0 * w0 + d1 * w1 + d2 * w2 + EPSF;
        float dd[NB] = {d0, d1, d2}, ww[NB] = {w0, w1, w2};
        float acc = 0.f;
        #pragma unroll
        for (int bi = 0; bi < NB; bi++) {
            float coef = (dd[bi] * ww[bi] / tw) / (dd[bi] + EPSF);
            acc += coef * g_n2u[((size_t)bi * NBATCH + b) * D2 + t];
        }
        f[t] = acc;
    }
    __syncthreads();
    float acc = 0.f;
    #pragma unroll
    for (int k = 0; k < D_N; k++) acc += f[k] * userW[k * D2 + t];
    if (t >= D_N) {
        #pragma unroll
        for (int k = 0; k < D_N; k++) acc += f[k] * W[k * D_N + (t - D_N)];
    } else {
        acc += uemb[(size_t)u * D_N + t];
    }
    g_uf[(size_t)b * D2 + t] = acc;

    float s1 = acc * sigW[t];
    float s2 = acc * acc;
    #pragma unroll
    for (int o = 16; o; o >>= 1) {
        s1 += __shfl_xor_sync(0xffffffffu, s1, o);
        s2 += __shfl_xor_sync(0xffffffffu, s2, o);
    }
    __shared__ float r1[4], r2[4];
    int wid = t >> 5;
    if ((t & 31) == 0) { r1[wid] = s1; r2[wid] = s2; }
    __syncthreads();
    if (t == 0) {
        g_sw[b]  = r1[0] + r1[1] + r1[2] + r1[3];
        g_ufn[b] = r2[0] + r2[1] + r2[2] + r2[3];
    }
}

// fused score2 + score1 + gate + L2
__global__ void k_scorefinal(const float* __restrict__ iemb, const int* __restrict__ user,
                             const int* __restrict__ item, float* __restrict__ out,
                             int out_size) {
    int w = (blockIdx.x * blockDim.x + threadIdx.x) >> 5;
    int lane = threadIdx.x & 31;
    int wlocal = threadIdx.x >> 5;
    __shared__ float l2s[8];
    float l2c = 0.f;
    if (w < NBATCH * NK) {
        int b = w / NK;
        int it = item[w];
        int r = g_u2slot[user[b]];
        float s2 = 0.f;
        #pragma unroll
        for (int bi = 0; bi < NB; bi++) {
            float4 a = ((const float4*)(g_i2u + ((size_t)bi * NBATCH + r) * D2))[lane];
            float4 v = (lane < 16)
                ? ((const float4*)(iemb + (size_t)it * D_N))[lane]
                : ((const float4*)(g_ii + (size_t)(bi * I_N + it) * D_N))[lane - 16];
            s2 += a.x * v.x + a.y * v.y + a.z * v.z + a.w * v.w;
        }
        float4 ua = ((const float4*)(g_uf  + (size_t)r  * D2))[lane];
        float4 iv = ((const float4*)(g_itf + (size_t)it * D2))[lane];
        float s1 = ua.x * iv.x + ua.y * iv.y + ua.z * iv.z + ua.w * iv.w;
        #pragma unroll
        for (int o = 16; o; o >>= 1) {
            s1 += __shfl_xor_sync(0xffffffffu, s1, o);
            s2 += __shfl_xor_sync(0xffffffffu, s2, o);
        }
        if (lane == 0) {
            float g = 1.f / (1.f + expf(-g_sw[r]));
            out[w] = s1 * g + (s2 * (1.f / 3.f)) * (1.f - g);
            l2c = REGF * (g_ufn[r] + g_itfn[it]);
        }
    }
    if (lane == 0) l2s[wlocal] = l2c;
    __syncthreads();
    if (threadIdx.x == 0 && out_size > NBATCH * NK) {
        float t = 0.f;
        #pragma unroll
        for (int i = 0; i < 8; i++) t += l2s[i];
        atomicAdd(&out[NBATCH * NK], t);
    }
}

// ---------------- launch ---------------------------------------------------
extern "C" void kernel_launch(void* const* d_in, const int* in_sizes, int n_in,
                              void* d_out, int out_size) {
    const float* user_emb = (const float*)d_in[0];
    const float* item_emb = (const float*)d_in[1];
    const float* ubd      = (const float*)d_in[2];
    const float* bw       = (const float*)d_in[3];
    const float* ig_deg   = (const float*)d_in[4];
    const float* ibW      = (const float*)d_in[5];
    const float* ipW      = (const float*)d_in[6];
    const float* W        = (const float*)d_in[7];
    const float* userW    = (const float*)d_in[8];
    const float* itemW    = (const float*)d_in[9];
    const float* sigW     = (const float*)d_in[10];
    const int*   ui_rows  = (const int*)d_in[11];
    const int*   ui_cols  = (const int*)d_in[12];
    const int*   ig_rows  = (const int*)d_in[13];
    const int*   ig_cols  = (const int*)d_in[14];
    const int*   trows    = (const int*)d_in[15];
    const int*   tcols    = (const int*)d_in[16];
    const int*   user     = (const int*)d_in[17];
    const int*   item     = (const int*)d_in[18];
    float* out = (float*)d_out;

    // One-time handles (first call = non-capturing correctness run;
    // capture call reuses — no resource-mgmt API during capture).
    static cudaStream_t s1 = nullptr, s2 = nullptr;
    static cudaEvent_t evF = nullptr, evG = nullptr, evT = nullptr;
    if (s1 == nullptr) {
        cudaStreamCreateWithFlags(&s1, cudaStreamNonBlocking);
        cudaStreamCreateWithFlags(&s2, cudaStreamNonBlocking);
        cudaEventCreateWithFlags(&evF, cudaEventDisableTiming);
        cudaEventCreateWithFlags(&evG, cudaEventDisableTiming);
        cudaEventCreateWithFlags(&evT, cudaEventDisableTiming);
    }

    // head (stream 0): fused init + scatter complete BEFORE the fork so the
    // critical-path fillb starts on a quiet chip (round-10 configuration)
    k_init<<<(NB * NBATCH * D2 + 255) / 256, 256>>>(out, out_size);
    k_scatter<<<(NBATCH + 255) / 256, 256>>>(user);
    cudaEventRecord(evF, 0);
    cudaStreamWaitEvent(s1, evF, 0);

    // ---- s1 (critical path): fused fill -> fused gather ----
    k_fillb<<<(NE_ALL / 8 + 255) / 256, 256, 0, s1>>>(ig_rows, ig_cols, trows, tcols);
    k_gather<<<(CNT_N * 32) / 256, 256, 0, s1>>>(item_emb, user_emb, ig_deg);
    cudaEventRecord(evG, s1);

    // ---- stream 0 (hidden under s1): filter + weight folds ----
    k_filter<<<(NB * NE_UI / 4 + 255) / 256, 256>>>(ui_rows, ui_cols);
    k_w1a<<<dim3(4, NB), 256>>>(ibW, ipW);
    k_w1b<<<dim3(4, NB), 256>>>(ipW);

    // ---- s2: itf (needs gather's g_if; concurrent with stream-0 tail) ----
    cudaStreamWaitEvent(s2, evG, 0);
    k_itf<<<(I_N + 31) / 32, 256, 0, s2>>>(item_emb, W, itemW);
    cudaEventRecord(evT, s2);

    // ---- stream 0 tail (needs g_ii / filter output) ----
    cudaStreamWaitEvent(0, evG, 0);
    k_ui_accum<<<512, 256>>>(item_emb);
    k_i2u<<<dim3(NBATCH / 32, NB), 256>>>(ubd, user);
    k_uf<<<NBATCH, 128>>>(user_emb, W, userW, sigW, user, ubd, bw);

    cudaStreamWaitEvent(0, evT, 0);
    k_scorefinal<<<(NBATCH * NK * 32 + 255) / 256, 256>>>(item_emb, user, item,
                                                          out, out_size);
}

// round 15
// speedup vs baseline: 1.3560x; 1.1958x over previous
#include <cuda_runtime.h>

#define U_N    100000
#define I_N    30000
#define NB     3
#define D_N    64
#define D2     128
#define NE_UI  500000
#define NE_IG  400000
#define NE_TR  1000000
#define NE_ALL (NB * NE_IG + NE_TR)
#define NBATCH 2048
#define NK     20
#define BK     128
#define CNT_N  ((NB + 1) * I_N)
#define EPSF   1e-8f
#define REGF   1e-4f

// ---------------- scratch (device globals; no allocation) ------------------
__device__ __align__(16) float g_ii   [NB * I_N * D_N];   // (A_ii@item_emb)/deg
__device__ __align__(16) float g_if   [I_N * D_N];        // train^T @ user_emb
__device__ __align__(16) float g_itf  [I_N * D2];
__device__               float g_itfn [I_N];
__device__               int   g_u2slot[U_N];
__device__ __align__(16) float g_n2u  [NB * NBATCH * D2]; // raw then normalized
__device__ __align__(16) float g_i2u  [NB * NBATCH * D2]; // n2u_norm @ W2
__device__ __align__(16) float g_ufeat[NBATCH * D_N];
__device__ __align__(16) float g_uf   [NBATCH * D2];
__device__               float g_sw   [NBATCH];
__device__               float g_ufn  [NBATCH];
__device__ __align__(16) float g_W1   [NB * D2 * D2];     // [ibW_top ; Wp@ibW_bot]
__device__ __align__(16) float g_W2   [NB * D2 * D2];     // + output-side Wp fold
// bucketed adjacency: rows 0..3*I_N-1 = ig behaviors, rows 3*I_N.. = train
__device__               int   g_cnt  [CNT_N + 1];        // +1: nhit counter
__device__               int   g_bkt  [(size_t)CNT_N * BK];
__device__               int   g_hit  [NB * NE_UI];

__device__ __forceinline__ void red_add4(float* p, float4 v) {
#if defined(__CUDA_ARCH__) && (__CUDA_ARCH__ >= 900)
    asm volatile("red.global.add.v4.f32 [%0], {%1,%2,%3,%4};"
                 :: "l"(p), "f"(v.x), "f"(v.y), "f"(v.z), "f"(v.w) : "memory");
#else
    atomicAdd(p + 0, v.x); atomicAdd(p + 1, v.y);
    atomicAdd(p + 2, v.z); atomicAdd(p + 3, v.w);
#endif
}

// ---------------- kernels --------------------------------------------------

// W1[bi] = [ibW_top ; Wp @ ibW_bot]
__global__ void k_w1a(const float* __restrict__ ibW, const float* __restrict__ ipW) {
    int gid = blockIdx.x * blockDim.x + threadIdx.x;
    if (gid >= NB * D2 * D2) return;
    int bi = gid / (D2 * D2);
    int rem = gid - bi * D2 * D2;
    int r = rem >> 7, c = rem & 127;
    const float* ibWb = ibW + (size_t)bi * D2 * D2;
    float v;
    if (r < 64) {
        v = ibWb[r * D2 + c];
    } else {
        const float* wp = ipW + (size_t)bi * D_N * D_N + (r - 64) * D_N;
        float acc = 0.f;
        #pragma unroll 8
        for (int k = 0; k < D_N; k++) acc += wp[k] * ibWb[(64 + k) * D2 + c];
        v = acc;
    }
    g_W1[gid] = v;
}

// W2[k][c<64] = W1[k][c]; W2[k][64+r] = sum_c W1[k][64+c] * Wp[r][c]
__global__ void k_w1b(const float* __restrict__ ipW) {
    int gid = blockIdx.x * blockDim.x + threadIdx.x;
    if (gid >= NB * D2 * D2) return;
    int bi = gid / (D2 * D2);
    int rem = gid - bi * D2 * D2;
    int k = rem >> 7, c = rem & 127;
    const float* W1b = g_W1 + (size_t)bi * D2 * D2 + k * D2;
    float v;
    if (c < 64) {
        v = W1b[c];
    } else {
        const float* wp = ipW + (size_t)bi * D_N * D_N + (c - 64) * D_N;
        float acc = 0.f;
        #pragma unroll 8
        for (int j = 0; j < D_N; j++) acc += W1b[64 + j] * wp[j];
        v = acc;
    }
    g_W2[gid] = v;
}

__global__ void k_scatter(const int* __restrict__ user, float* out, int out_size) {
    int b = blockIdx.x * blockDim.x + threadIdx.x;
    if (b < NBATCH) atomicMin(&g_u2slot[user[b]], b);
    if (b == 0 && out_size > NBATCH * NK) out[NBATCH * NK] = 0.f;
}

// fused bucket fill over all 2.2M edges (4/thread, segment-aligned)
__global__ void k_fillb(const int* __restrict__ ig_rows, const int* __restrict__ ig_cols,
                        const int* __restrict__ trows, const int* __restrict__ tcols) {
    int i = (blockIdx.x * blockDim.x + threadIdx.x) * 4;
    if (i >= NE_ALL) return;
    int4 r4, c4;
    int tb;
    if (i < NB * NE_IG) {
        tb = i / NE_IG;
        r4 = *(const int4*)(ig_rows + i);
        c4 = *(const int4*)(ig_cols + i);
    } else {
        int j = i - NB * NE_IG;
        tb = NB;
        r4 = *(const int4*)(tcols + j);   // dest = item (tcols)
        c4 = *(const int4*)(trows + j);   // src  = user (trows)
    }
    int base = tb * I_N;
    int rr[4] = {r4.x, r4.y, r4.z, r4.w};
    int cc[4] = {c4.x, c4.y, c4.z, c4.w};
    #pragma unroll
    for (int j = 0; j < 4; j++) {
        int row = base + rr[j];
        int slot = atomicAdd(&g_cnt[row], 1);
        if (slot < BK) g_bkt[(size_t)row * BK + slot] = cc[j];
    }
}

// paired-edge float4 warp gather: lanes 0-15 even edges, 16-31 odd edges,
// each lane loads one float4 (16B) row slice; halves combined via shfl_xor(16)
__global__ void k_gather(const float* __restrict__ iemb, const float* __restrict__ uemb,
                         const float* __restrict__ deg) {
    int w = (blockIdx.x * blockDim.x + threadIdx.x) >> 5;
    int lane = threadIdx.x & 31;
    if (w >= CNT_N) return;
    int bi = w / I_N, r = w - bi * I_N;
    int cnt = g_cnt[w]; if (cnt > BK) cnt = BK;
    const int* src = g_bkt + (size_t)w * BK;
    const float* emb = (bi < NB) ? iemb : uemb;
    int half = lane >> 4;      // 0: even edge of pair, 1: odd edge
    int qcol = lane & 15;      // float4 slot within the 64-float row
    float4 accA = {0.f, 0.f, 0.f, 0.f};
    float4 accB = {0.f, 0.f, 0.f, 0.f};
    for (int j = 0; j < cnt; j += 32) {
        int m = cnt - j; if (m > 32) m = 32;
        int sidx = (lane < m) ? src[j + lane] : 0;
        int q = 0;
        for (; q + 4 <= m; q += 4) {
            int sA = __shfl_sync(0xffffffffu, sidx, q + half);
            int sB = __shfl_sync(0xffffffffu, sidx, q + 2 + half);
            float4 vA = ((const float4*)(emb + (size_t)sA * D_N))[qcol];
            float4 vB = ((const float4*)(emb + (size_t)sB * D_N))[qcol];
            accA.x += vA.x; accA.y += vA.y; accA.z += vA.z; accA.w += vA.w;
            accB.x += vB.x; accB.y += vB.y; accB.z += vB.z; accB.w += vB.w;
        }
        for (; q < m; q += 2) {
            int idx = q + half;
            int sA = __shfl_sync(0xffffffffu, sidx, (idx < m) ? idx : q);
            float4 vA = ((const float4*)(emb + (size_t)sA * D_N))[qcol];
            if (idx < m) {
                accA.x += vA.x; accA.y += vA.y; accA.z += vA.z; accA.w += vA.w;
            }
        }
    }
    float4 acc = {accA.x + accB.x, accA.y + accB.y, accA.z + accB.z, accA.w + accB.w};
    acc.x += __shfl_xor_sync(0xffffffffu, acc.x, 16);
    acc.y += __shfl_xor_sync(0xffffffffu, acc.y, 16);
    acc.z += __shfl_xor_sync(0xffffffffu, acc.z, 16);
    acc.w += __shfl_xor_sync(0xffffffffu, acc.w, 16);
    if (lane < 16) {
        if (bi < NB) {
            float inv = 1.f / (deg[w] + EPSF);   // deg laid out [NB][I_N] == w
            acc.x *= inv; acc.y *= inv; acc.z *= inv; acc.w *= inv;
            ((float4*)(g_ii + (size_t)w * D_N))[qcol] = acc;
        } else {
            ((float4*)(g_if + (size_t)r * D_N))[qcol] = acc;
        }
    }
}

// scan ui edges, compact hits (slot,col) keys (warp-aggregated append)
__global__ void k_filter(const int* __restrict__ rows, const int* __restrict__ cols) {
    int i = (blockIdx.x * blockDim.x + threadIdx.x) * 4;
    int lane = threadIdx.x & 31;
    bool in = (i < NB * NE_UI);
    int4 r = in ? *(const int4*)(rows + i) : make_int4(0, 0, 0, 0);
    int bi = in ? (i / NE_UI) : 0;
    int rb = bi * NBATCH;
    int rr[4] = {r.x, r.y, r.z, r.w};
    #pragma unroll
    for (int j = 0; j < 4; j++) {
        int sl = in ? g_u2slot[rr[j]] : 0x7fffffff;
        bool hit = sl < NBATCH;
        unsigned m = __ballot_sync(0xffffffffu, hit);
        if (m) {
            int leader = __ffs(m) - 1;
            int base;
            if (lane == leader) base = atomicAdd(&g_cnt[CNT_N], __popc(m));
            base = __shfl_sync(0xffffffffu, base, leader);
            if (hit) {
                int col = cols[i + j];
                g_hit[base + __popc(m & ((1u << lane) - 1))] = ((rb + sl) << 15) | col;
            }
        }
    }
}

// accumulate hit edges: n2u[rs] += [item_emb[col] | g_ii[bi][col]]
__global__ void k_ui_accum(const float* __restrict__ iemb) {
    int nw = (gridDim.x * blockDim.x) >> 5;
    int w = (blockIdx.x * blockDim.x + threadIdx.x) >> 5;
    int lane = threadIdx.x & 31;
    int n = g_cnt[CNT_N];
    for (int h = w; h < n; h += nw) {
        int key = g_hit[h];
        int col = key & 0x7fff;
        int rs = key >> 15;
        int bi = rs >> 11;
        float* base = g_n2u + (size_t)rs * D2;
        float4 v;
        float* dst;
        if (lane < 16) {
            v = ((const float4*)(iemb + (size_t)col * D_N))[lane];
            dst = base + lane * 4;
        } else {
            v = ((const float4*)(g_ii + (size_t)(bi * I_N + col) * D_N))[lane - 16];
            dst = base + 64 + (lane - 16) * 4;
        }
        red_add4(dst, v);
    }
}

// normalize n2u by denom; user_feature (rep slots only; rep inlined)
__global__ void k_norm(const float* __restrict__ ubd, const float* __restrict__ bw,
                       const int* __restrict__ user) {
    int b = blockIdx.x;
    int u = user[b];
    if (g_u2slot[u] != b) return;
    int t = threadIdx.x;
    float d0 = ubd[u * NB + 0], d1 = ubd[u * NB + 1], d2 = ubd[u * NB + 2];
    float w0 = bw[0], w1 = bw[1], w2 = bw[2];
    float tw = d0 * w0 + d1 * w1 + d2 * w2 + EPSF;
    float dd[NB] = {d0, d1, d2}, ww[NB] = {w0, w1, w2};
    float uacc = 0.f;
    #pragma unroll
    for (int bi = 0; bi < NB; bi++) {
        float inv = 1.f / (dd[bi] + EPSF);
        size_t o = ((size_t)bi * NBATCH + b) * D2 + t;
        float v = g_n2u[o] * inv;
        g_n2u[o] = v;
        if (t < D_N) uacc += (dd[bi] * ww[bi] / tw) * v;
    }
    if (t < D_N) g_ufeat[b * D_N + t] = uacc;
}

// i2u[bi] = n2u[bi] @ W2[bi]  (fully folded weight)
__global__ void k_i2u() {
    int bi = blockIdx.y;
    int s0 = blockIdx.x * 32;
    const float* Wb = g_W2 + (size_t)bi * D2 * D2;
    const float* N  = g_n2u + ((size_t)bi * NBATCH + s0) * D2;
    __shared__ float shW[64 * D2];
    __shared__ float shN[32 * 64];
    int t = threadIdx.x;
    int cg = t & 31, sg = t >> 5;
    float acc[4][4];
    #pragma unroll
    for (int i = 0; i < 4; i++)
        #pragma unroll
        for (int j = 0; j < 4; j++) acc[i][j] = 0.f;
    for (int kp = 0; kp < 2; kp++) {
        __syncthreads();
        for (int p = t; p < 64 * D2; p += 256) shW[p] = Wb[kp * 64 * D2 + p];
        for (int p = t; p < 32 * 64; p += 256)
            shN[p] = N[(size_t)(p >> 6) * D2 + kp * 64 + (p & 63)];
        __syncthreads();
        for (int k = 0; k < 64; k++) {
            float4 w = ((const float4*)(shW + k * D2))[cg];
            #pragma unroll
            for (int i = 0; i < 4; i++) {
                float a = shN[(sg * 4 + i) * 64 + k];
                acc[i][0] += a * w.x; acc[i][1] += a * w.y;
                acc[i][2] += a * w.z; acc[i][3] += a * w.w;
            }
        }
    }
    float* O = g_i2u + ((size_t)bi * NBATCH + s0) * D2;
    #pragma unroll
    for (int i = 0; i < 4; i++) {
        float4 o = {acc[i][0], acc[i][1], acc[i][2], acc[i][3]};
        ((float4*)(O + (size_t)(sg * 4 + i) * D2))[cg] = o;
    }
}

__global__ void k_itf(const float* __restrict__ iemb, const float* __restrict__ W,
                      const float* __restrict__ itemW) {
    __shared__ float shM[D_N * D2];
    __shared__ float shA[32 * D_N];
    int t = threadIdx.x;
    for (int p = t; p < D_N * D2; p += 256) {
        int k = p >> 7, j = p & 127;
        float m = itemW[p];
        if (j >= D_N) m += W[k * D_N + (j - D_N)];
        shM[p] = m;
    }
    int r0 = blockIdx.x * 32;
    for (int p = t; p < 32 * D_N; p += 256) {
        int rr = p >> 6, cc = p & 63;
        int row = r0 + rr;
        shA[p] = (row < I_N) ? g_if[(size_t)row * D_N + cc] : 0.f;
    }
    __syncthreads();
    int cg = t & 31, sg = t >> 5;
    float acc[4][4];
    #pragma unroll
    for (int i = 0; i < 4; i++)
        #pragma unroll
        for (int j = 0; j < 4; j++) acc[i][j] = 0.f;
    for (int k = 0; k < D_N; k++) {
        float4 w = ((const float4*)(shM + k * D2))[cg];
        #pragma unroll
        for (int i = 0; i < 4; i++) {
            float a = shA[(sg * 4 + i) * D_N + k];
            acc[i][0] += a * w.x; acc[i][1] += a * w.y;
            acc[i][2] += a * w.z; acc[i][3] += a * w.w;
        }
    }
    #pragma unroll
    for (int i = 0; i < 4; i++) {
        int row = r0 + sg * 4 + i;
        if (row >= I_N) continue;
        float4 v = {acc[i][0], acc[i][1], acc[i][2], acc[i][3]};
        if (cg < 16) {
            float4 e = ((const float4*)(iemb + (size_t)row * D_N))[cg];
            v.x += e.x; v.y += e.y; v.z += e.z; v.w += e.w;
        }
        ((float4*)(g_itf + (size_t)row * D2))[cg] = v;
        float n = v.x * v.x + v.y * v.y + v.z * v.z + v.w * v.w;
        #pragma unroll
        for (int o = 16; o; o >>= 1) n += __shfl_xor_sync(0xffffffffu, n, o);
        if ((t & 31) == 0) g_itfn[row] = n;
    }
}

__global__ void k_uf(const float* __restrict__ uemb, const float* __restrict__ W,
                     const float* __restrict__ userW, const float* __restrict__ sigW,
                     const int* __restrict__ user) {
    int b = blockIdx.x;
    int u = user[b];
    if (g_u2slot[u] != b) return;
    int t = threadIdx.x;
    __shared__ float f[D_N];
    if (t < D_N) f[t] = g_ufeat[b * D_N + t];
    __syncthreads();
    float acc = 0.f;
    #pragma unroll
    for (int k = 0; k < D_N; k++) acc += f[k] * userW[k * D2 + t];
    if (t >= D_N) {
        #pragma unroll
        for (int k = 0; k < D_N; k++) acc += f[k] * W[k * D_N + (t - D_N)];
    } else {
        acc += uemb[(size_t)u * D_N + t];
    }
    g_uf[(size_t)b * D2 + t] = acc;

    float s1 = acc * sigW[t];
    float s2 = acc * acc;
    #pragma unroll
    for (int o = 16; o; o >>= 1) {
        s1 += __shfl_xor_sync(0xffffffffu, s1, o);
        s2 += __shfl_xor_sync(0xffffffffu, s2, o);
    }
    __shared__ float r1[4], r2[4];
    int wid = t >> 5;
    if ((t & 31) == 0) { r1[wid] = s1; r2[wid] = s2; }
    __syncthreads();
    if (t == 0) {
        g_sw[b]  = r1[0] + r1[1] + r1[2] + r1[3];
        g_ufn[b] = r2[0] + r2[1] + r2[2] + r2[3];
    }
}

// fused score2 + score1 + gate + L2
__global__ void k_scorefinal(const float* __restrict__ iemb, const int* __restrict__ user,
                             const int* __restrict__ item, float* __restrict__ out,
                             int out_size) {
    int w = (blockIdx.x * blockDim.x + threadIdx.x) >> 5;
    int lane = threadIdx.x & 31;
    int wlocal = threadIdx.x >> 5;
    __shared__ float l2s[8];
    float l2c = 0.f;
    if (w < NBATCH * NK) {
        int b = w / NK;
        int it = item[w];
        int r = g_u2slot[user[b]];
        float s2 = 0.f;
        #pragma unroll
        for (int bi = 0; bi < NB; bi++) {
            float4 a = ((const float4*)(g_i2u + ((size_t)bi * NBATCH + r) * D2))[lane];
            float4 v = (lane < 16)
                ? ((const float4*)(iemb + (size_t)it * D_N))[lane]
                : ((const float4*)(g_ii + (size_t)(bi * I_N + it) * D_N))[lane - 16];
            s2 += a.x * v.x + a.y * v.y + a.z * v.z + a.w * v.w;
        }
        float4 ua = ((const float4*)(g_uf  + (size_t)r  * D2))[lane];
        float4 iv = ((const float4*)(g_itf + (size_t)it * D2))[lane];
        float s1 = ua.x * iv.x + ua.y * iv.y + ua.z * iv.z + ua.w * iv.w;
        #pragma unroll
        for (int o = 16; o; o >>= 1) {
            s1 += __shfl_xor_sync(0xffffffffu, s1, o);
            s2 += __shfl_xor_sync(0xffffffffu, s2, o);
        }
        if (lane == 0) {
            float g = 1.f / (1.f + expf(-g_sw[r]));
            out[w] = s1 * g + (s2 * (1.f / 3.f)) * (1.f - g);
            l2c = REGF * (g_ufn[r] + g_itfn[it]);
        }
    }
    if (lane == 0) l2s[wlocal] = l2c;
    __syncthreads();
    if (threadIdx.x == 0 && out_size > NBATCH * NK) {
        float t = 0.f;
        #pragma unroll
        for (int i = 0; i < 8; i++) t += l2s[i];
        atomicAdd(&out[NBATCH * NK], t);
    }
}

// ---------------- launch ---------------------------------------------------
extern "C" void kernel_launch(void* const* d_in, const int* in_sizes, int n_in,
                              void* d_out, int out_size) {
    const float* user_emb = (const float*)d_in[0];
    const float* item_emb = (const float*)d_in[1];
    const float* ubd      = (const float*)d_in[2];
    const float* bw       = (const float*)d_in[3];
    const float* ig_deg   = (const float*)d_in[4];
    const float* ibW      = (const float*)d_in[5];
    const float* ipW      = (const float*)d_in[6];
    const float* W        = (const float*)d_in[7];
    const float* userW    = (const float*)d_in[8];
    const float* itemW    = (const float*)d_in[9];
    const float* sigW     = (const float*)d_in[10];
    const int*   ui_rows  = (const int*)d_in[11];
    const int*   ui_cols  = (const int*)d_in[12];
    const int*   ig_rows  = (const int*)d_in[13];
    const int*   ig_cols  = (const int*)d_in[14];
    const int*   trows    = (const int*)d_in[15];
    const int*   tcols    = (const int*)d_in[16];
    const int*   user     = (const int*)d_in[17];
    const int*   item     = (const int*)d_in[18];
    float* out = (float*)d_out;

    // One-time handles + symbol addresses (first call = non-capturing
    // correctness run; capture call reuses — no resource-mgmt API in capture).
    static cudaStream_t s1 = nullptr, s2 = nullptr;
    static cudaEvent_t evFork = nullptr, evG = nullptr, evT = nullptr;
    static void *p_u2slot, *p_n2u, *p_cnt;
    if (s1 == nullptr) {
        cudaStreamCreateWithFlags(&s1, cudaStreamNonBlocking);
        cudaStreamCreateWithFlags(&s2, cudaStreamNonBlocking);
        cudaEventCreateWithFlags(&evFork, cudaEventDisableTiming);
        cudaEventCreateWithFlags(&evG, cudaEventDisableTiming);
        cudaEventCreateWithFlags(&evT, cudaEventDisableTiming);
        cudaGetSymbolAddress(&p_u2slot, g_u2slot);
        cudaGetSymbolAddress(&p_n2u,    g_n2u);
        cudaGetSymbolAddress(&p_cnt,    g_cnt);
    }

    cudaMemsetAsync(p_u2slot, 0x7f, U_N * sizeof(int), 0);        // "inf" slots
    cudaMemsetAsync(p_n2u, 0, NB * NBATCH * D2 * sizeof(float), 0);
    cudaMemsetAsync(p_cnt, 0, (CNT_N + 1) * sizeof(int), 0);      // counts + nhit

    cudaEventRecord(evFork, 0);
    cudaStreamWaitEvent(s1, evFork, 0);
    cudaStreamWaitEvent(s2, evFork, 0);

    // ---- s1: bucket fill -> fused gather ----
    k_fillb<<<(NE_ALL / 4 + 255) / 256, 256, 0, s1>>>(ig_rows, ig_cols, trows, tcols);
    k_gather<<<(CNT_N * 32) / 256, 256, 0, s1>>>(item_emb, user_emb, ig_deg);
    cudaEventRecord(evG, s1);

    // ---- stream 0: weight folds + user scatter + ui filter (independent) ----
    k_w1a<<<(NB * D2 * D2 + 255) / 256, 256>>>(ibW, ipW);
    k_w1b<<<(NB * D2 * D2 + 255) / 256, 256>>>(ipW);
    k_scatter<<<(NBATCH + 255) / 256, 256>>>(user, out, out_size);
    k_filter<<<(NB * NE_UI / 4 + 255) / 256, 256>>>(ui_rows, ui_cols);

    // ---- s2: itf (needs gather's g_if) ----
    cudaStreamWaitEvent(s2, evG, 0);
    k_itf<<<(I_N + 31) / 32, 256, 0, s2>>>(item_emb, W, itemW);
    cudaEventRecord(evT, s2);

    // ---- stream 0 tail ----
    cudaStreamWaitEvent(0, evG, 0);
    k_ui_accum<<<512, 256>>>(item_emb);
    k_norm<<<NBATCH, 128>>>(ubd, bw, user);
    k_i2u<<<dim3(NBATCH / 32, NB), 256>>>();
    k_uf<<<NBATCH, 128>>>(user_emb, W, userW, sigW, user);

    cudaStreamWaitEvent(0, evT, 0);
    k_scorefinal<<<(NBATCH * NK * 32 + 255) / 256, 256>>>(item_emb, user, item,
                                                          out, out_size);
}